// round 1
// baseline (speedup 1.0000x reference)
#include <cuda_runtime.h>
#include <cuda_bf16.h>
#include <cstddef>

// ---------------------------------------------------------------------------
// NetAE: batch-1 MoE-style forward. Entirely HBM-bound GEMV chain (~596MB of
// fp32 weights per call). Strategy: generic split-K GEMV with float4-coalesced
// weight reads + tiny finalize kernels fusing bias / relu / attention epilogues.
// No atomics anywhere -> deterministic. All scratch in __device__ globals.
// ---------------------------------------------------------------------------

#define D_IN   2048
#define D_H    2048
#define D_V    2048
#define D_A    256
#define N_EXP  16
#define N_TASK 10
#define D_T    2048
#define D_OUT  512

// Scratch (reused across stages; max concurrent need = 16*8*2048 floats)
__device__ float g_part[16 * 8 * 2048];   // split-K partials (1 MB)
__device__ float g_h1[D_H];
__device__ float g_h2[D_H];
__device__ float g_e[N_EXP * D_H];
__device__ float g_expkq[N_EXP];
__device__ float g_res[D_V];
__device__ float g_t[D_T];

// ---------------------------------------------------------------------------
// Generic split-K GEMV partial kernel.
//   W: [B][K][N] row-major.  x: per-batch vector (stride xStride; 0 = shared).
//   grid = (N / (4*blockDim.x), S, B). Each block: RPS rows x 4*blockDim.x cols.
//   partial[(b*S + s)*N + j] = sum_{i in slice} x[i] * W[b][i][j]
// Coalesced: 4*blockDim.x consecutive floats per row via float4.
// ---------------------------------------------------------------------------
__global__ __launch_bounds__(128)
void gemv_part(const float* __restrict__ W, const float* __restrict__ x,
               float* __restrict__ part, int N, int RPS, int xStride)
{
    __shared__ float sx[256];                 // RPS <= 256 always
    const int tid   = threadIdx.x;
    const int slice = blockIdx.y;
    const int b     = blockIdx.z;
    const int S     = gridDim.y;
    const int i0    = slice * RPS;

    const float* xb = x + (size_t)b * xStride + i0;
    for (int r = tid; r < RPS; r += blockDim.x) sx[r] = xb[r];
    __syncthreads();

    const int j = (blockIdx.x * blockDim.x + tid) * 4;
    const size_t K = (size_t)S * RPS;
    const float* Wp = W + (size_t)b * K * N + (size_t)i0 * N + j;

    float4 acc = make_float4(0.f, 0.f, 0.f, 0.f);
    #pragma unroll 8
    for (int r = 0; r < RPS; r++) {
        const float4 w = *reinterpret_cast<const float4*>(Wp + r * N);
        const float xi = sx[r];
        acc.x += xi * w.x;
        acc.y += xi * w.y;
        acc.z += xi * w.z;
        acc.w += xi * w.w;
    }
    float* P = part + ((size_t)(b * S + slice)) * N + j;
    *reinterpret_cast<float4*>(P) = acc;
}

// Reduce split-K partials, add bias, optional relu.
// idx covers B*N outputs; bias indexed flat [B*N]; partial layout [(b*S+s)*N + j].
__global__ void fin_reduce(const float* __restrict__ part, const float* __restrict__ bias,
                           float* __restrict__ out, int N, int S, int doRelu)
{
    const int idx = blockIdx.x * blockDim.x + threadIdx.x;
    const int b = idx / N;
    const int j = idx - b * N;
    float v = bias[idx];
    const float* p = part + (size_t)b * S * N + j;
    #pragma unroll 4
    for (int s = 0; s < S; s++) v += p[s * N];
    if (doRelu) v = fmaxf(v, 0.f);
    out[idx] = v;
}

// Attention scores: expkq[n] = sum_a (k[n,a]) * q[a]
//   k[n,a] = b_k[n,a] + sum_s part[(n*S+s)*256 + a]
//   q[a]   = W_q[t][t][a] + b_q[t][a]   (one-hot @ W_q[t] selects row t)
// One warp per expert; 512 threads, 1 block.
__global__ void fin_expkq(const float* __restrict__ part, int S,
                          const float* __restrict__ b_k,
                          const float* __restrict__ W_q,
                          const float* __restrict__ b_q,
                          const int* __restrict__ task_id,
                          float* __restrict__ expkq)
{
    const int w = threadIdx.x >> 5;   // expert (0..15)
    const int l = threadIdx.x & 31;
    const int t = *task_id;
    float sum = 0.f;
    for (int a = l; a < D_A; a += 32) {
        float k = b_k[w * D_A + a];
        const float* p = part + ((size_t)w * S) * D_A + a;
        for (int s = 0; s < S; s++) k += p[s * D_A];
        const float q = W_q[((size_t)t * N_TASK + t) * D_A + a] + b_q[t * D_A + a];
        sum += k * q;
    }
    #pragma unroll
    for (int off = 16; off; off >>= 1) sum += __shfl_xor_sync(0xFFFFFFFFu, sum, off);
    if (l == 0) expkq[w] = sum;
}

// res[j] = sum_n expkq[n] * (b_v[n,j] + sum_s part[(n*S+s)*N + j])
__global__ void fin_res(const float* __restrict__ part, const float* __restrict__ b_v,
                        const float* __restrict__ expkq, float* __restrict__ res,
                        int N, int S)
{
    const int j = blockIdx.x * blockDim.x + threadIdx.x;
    float r = 0.f;
    for (int n = 0; n < N_EXP; n++) {
        float v = b_v[n * N + j];
        const float* p = part + ((size_t)n * S) * N + j;
        #pragma unroll
        for (int s = 0; s < 8; s++) v += p[s * N];
        r += expkq[n] * v;
    }
    res[j] = r;
}

extern "C" void kernel_launch(void* const* d_in, const int* in_sizes, int n_in,
                              void* d_out, int out_size)
{
    const float* x     = (const float*)d_in[0];
    const float* W1    = (const float*)d_in[1];
    const float* b1    = (const float*)d_in[2];
    const float* W2    = (const float*)d_in[3];
    const float* b2    = (const float*)d_in[4];
    const float* W_exp = (const float*)d_in[5];
    const float* b_exp = (const float*)d_in[6];
    const float* W_v   = (const float*)d_in[7];
    const float* b_v   = (const float*)d_in[8];
    const float* W_k   = (const float*)d_in[9];
    const float* b_k   = (const float*)d_in[10];
    const float* W_q   = (const float*)d_in[11];
    const float* b_q   = (const float*)d_in[12];
    const float* W_t   = (const float*)d_in[13];
    const float* b_t   = (const float*)d_in[14];
    const float* W_l   = (const float*)d_in[15];
    const float* b_l   = (const float*)d_in[16];
    const int*   tid   = (const int*)d_in[17];
    float* out = (float*)d_out;

    float *part, *h1, *h2, *e, *ekq, *res, *tw;
    cudaGetSymbolAddress((void**)&part, g_part);
    cudaGetSymbolAddress((void**)&h1,   g_h1);
    cudaGetSymbolAddress((void**)&h2,   g_h2);
    cudaGetSymbolAddress((void**)&e,    g_e);
    cudaGetSymbolAddress((void**)&ekq,  g_expkq);
    cudaGetSymbolAddress((void**)&res,  g_res);
    cudaGetSymbolAddress((void**)&tw,   g_t);

    // A: h1 = relu(x @ W1 + b1)   [16 MB]   grid(4,32,1), 64 rows/slice
    gemv_part<<<dim3(4, 32, 1), 128>>>(W1, x, part, D_H, 64, 0);
    fin_reduce<<<D_H / 256, 256>>>(part, b1, h1, D_H, 32, 1);

    // B: h2 = relu(h1 @ W2 + b2)  [16 MB]
    gemv_part<<<dim3(4, 32, 1), 128>>>(W2, h1, part, D_H, 64, 0);
    fin_reduce<<<D_H / 256, 256>>>(part, b2, h2, D_H, 32, 1);

    // C: e[n] = relu(h2 @ W_exp[n] + b_exp[n])  [256 MB]  grid(4,8,16), 256 rows/slice
    gemv_part<<<dim3(4, 8, 16), 128>>>(W_exp, h2, part, D_H, 256, 0);
    fin_reduce<<<(N_EXP * D_H) / 256, 256>>>(part, b_exp, e, D_H, 8, 1);

    // D: expkq[n] = (e[n] @ W_k[n] + b_k[n]) . q   [32 MB]  grid(1,32,16), 64 rows/slice
    gemv_part<<<dim3(1, 32, 16), 64>>>(W_k, e, part, D_A, 64, D_H);
    fin_expkq<<<1, 512>>>(part, 32, b_k, W_q, b_q, tid, ekq);

    // E: res = sum_n expkq[n] * (e[n] @ W_v[n] + b_v[n])  [256 MB]
    gemv_part<<<dim3(4, 8, 16), 128>>>(W_v, e, part, D_V, 256, D_H);
    fin_res<<<D_V / 256, 256>>>(part, b_v, ekq, res, D_V, 8);

    // F: t = relu(res @ W_t + b_t)  [16 MB]
    gemv_part<<<dim3(4, 32, 1), 128>>>(W_t, res, part, D_T, 64, 0);
    fin_reduce<<<D_T / 256, 256>>>(part, b_t, tw, D_T, 32, 1);

    // G: out = t @ W_l + b_l  [4 MB]  grid(1,64,1), 32 rows/slice
    gemv_part<<<dim3(1, 64, 1), 128>>>(W_l, tw, part, D_OUT, 32, 0);
    fin_reduce<<<D_OUT / 256, 256>>>(part, b_l, out, D_OUT, 64, 0);
}

// round 2
// speedup vs baseline: 2.0302x; 2.0302x over previous
#include <cuda_runtime.h>
#include <cuda_bf16.h>
#include <cstddef>

// NetAE batch-1 forward: HBM-bound GEMV chain (~596MB fp32 weights/call).
// Split-K GEMV with the PREVIOUS stage's split-K reduction + bias + relu fused
// into the x-staging prologue of the consuming kernel (no standalone finalize
// kernels -> no serialized latency-bound launches). float4-coalesced weight
// reads, unroll-16, >=7 blocks/SM on the 256MB stages. No atomics.

#define D_H    2048
#define D_A    256
#define N_EXP  16
#define D_OUT  512

__device__ float g_pA[64 * 2048];
__device__ float g_pB[64 * 2048];
__device__ float g_pC[16 * 16 * 2048];
__device__ float g_pD[16 * 32 * 256];
__device__ float g_pE[16 * 16 * 2048];
__device__ float g_pF[64 * 2048];
__device__ float g_pG[128 * 512];
__device__ float g_ekq[16];

// ---------------------------------------------------------------------------
// Generic split-K GEMV with fused x-staging.
//   MODE 0: x direct.
//   MODE 1: x[r] = [relu](biasx[bb*NPREV+i0+r] + sum_{s<SPREV} xsrc[(bb*SPREV+s)*NPREV + i0+r])
//   MODE 2: x[r] = sum_{s<SPREV} xsrc[s*NPREV + i0+r] + sum_n ekq[n]*bv[n*NPREV + i0+r]
// W: [B][K][N] row-major, K = gridDim.y * RPS. Each block: RPS rows x 4*BLK cols.
// Output partial: partOut[(b*S + slice)*N + j..j+3] (float4, no atomics).
// ---------------------------------------------------------------------------
template<int BLK, int RPS, int N, int MODE, int SPREV, int NPREV,
         bool RELU_X, bool SCALE_OUT, bool PREV_PER_B>
__global__ __launch_bounds__(BLK)
void gemv_k(const float* __restrict__ W,
            const float* __restrict__ xsrc,
            const float* __restrict__ biasx,
            const float* __restrict__ bv,
            const float* __restrict__ ekq,
            float* __restrict__ partOut)
{
    __shared__ float sx[RPS];
    __shared__ float sxp[BLK];
    const int tid   = threadIdx.x;
    const int slice = blockIdx.y;
    const int b     = blockIdx.z;
    const int S     = gridDim.y;
    const int i0    = slice * RPS;
    const int K     = S * RPS;

    if constexpr (MODE == 0) {
        for (int r = tid; r < RPS; r += BLK) sx[r] = xsrc[i0 + r];
        __syncthreads();
    } else if constexpr (MODE == 1) {
        constexpr int CH = BLK / RPS;
        const int r = tid % RPS;
        const int c = tid / RPS;
        const int bb = PREV_PER_B ? b : 0;
        const float* p = xsrc + ((size_t)bb * SPREV) * NPREV + (i0 + r);
        float v = 0.f;
        #pragma unroll
        for (int s = c; s < SPREV; s += CH) v += p[(size_t)s * NPREV];
        sxp[tid] = v;
        __syncthreads();
        if (tid < RPS) {
            float v2 = biasx[(size_t)(PREV_PER_B ? b : 0) * NPREV + i0 + tid];
            #pragma unroll
            for (int cc = 0; cc < CH; cc++) v2 += sxp[tid + cc * RPS];
            sx[tid] = RELU_X ? fmaxf(v2, 0.f) : v2;
        }
        __syncthreads();
    } else {  // MODE 2: res = flat reduce over 256 scaled V-partials + ekq-weighted b_v
        constexpr int CH = BLK / RPS;
        const int r = tid % RPS;
        const int c = tid / RPS;
        const float* p = xsrc + (i0 + r);
        float v = 0.f;
        #pragma unroll 16
        for (int s = c; s < SPREV; s += CH) v += p[(size_t)s * NPREV];
        sxp[tid] = v;
        __syncthreads();
        if (tid < RPS) {
            float v2 = 0.f;
            #pragma unroll
            for (int cc = 0; cc < CH; cc++) v2 += sxp[tid + cc * RPS];
            #pragma unroll
            for (int n = 0; n < N_EXP; n++)
                v2 += ekq[n] * bv[(size_t)n * NPREV + i0 + tid];
            sx[tid] = v2;
        }
        __syncthreads();
    }

    const int j = (blockIdx.x * BLK + tid) * 4;
    const float* Wp = W + (size_t)b * K * N + (size_t)i0 * N + j;
    float4 acc = make_float4(0.f, 0.f, 0.f, 0.f);
    #pragma unroll 16
    for (int rr = 0; rr < RPS; rr++) {
        const float4 w = *reinterpret_cast<const float4*>(Wp + (size_t)rr * N);
        const float xi = sx[rr];
        acc.x += xi * w.x;
        acc.y += xi * w.y;
        acc.z += xi * w.z;
        acc.w += xi * w.w;
    }
    if constexpr (SCALE_OUT) {
        const float sc = ekq[b];
        acc.x *= sc; acc.y *= sc; acc.z *= sc; acc.w *= sc;
    }
    *reinterpret_cast<float4*>(partOut + ((size_t)(b * S + slice)) * N + j) = acc;
}

// expkq[n] = (b_k[n] + reduce_s partD[n]) . (W_q[t][t] + b_q[t]);  1 block, 512 thr.
__global__ void fin_expkq(const float* __restrict__ part,
                          const float* __restrict__ b_k,
                          const float* __restrict__ W_q,
                          const float* __restrict__ b_q,
                          const int* __restrict__ task_id,
                          float* __restrict__ expkq)
{
    const int w = threadIdx.x >> 5;
    const int l = threadIdx.x & 31;
    const int t = *task_id;
    float sum = 0.f;
    #pragma unroll
    for (int aa = 0; aa < 8; aa++) {
        const int a = aa * 32 + l;
        float k = b_k[w * D_A + a];
        const float* p = part + ((size_t)w * 32) * D_A + a;
        #pragma unroll
        for (int s = 0; s < 32; s++) k += p[(size_t)s * D_A];
        const float q = W_q[((size_t)t * 10 + t) * D_A + a] + b_q[t * D_A + a];
        sum += k * q;
    }
    #pragma unroll
    for (int off = 16; off; off >>= 1) sum += __shfl_xor_sync(0xFFFFFFFFu, sum, off);
    if (l == 0) expkq[w] = sum;
}

// out[j] = b_l[j] + reduce_{s<128} partG[s*512 + j]
__global__ void fin_out(const float* __restrict__ part,
                        const float* __restrict__ b_l,
                        float* __restrict__ out)
{
    const int j = blockIdx.x * 128 + threadIdx.x;
    float v = b_l[j];
    #pragma unroll 16
    for (int s = 0; s < 128; s++) v += part[(size_t)s * D_OUT + j];
    out[j] = v;
}

extern "C" void kernel_launch(void* const* d_in, const int* in_sizes, int n_in,
                              void* d_out, int out_size)
{
    const float* x     = (const float*)d_in[0];
    const float* W1    = (const float*)d_in[1];
    const float* b1    = (const float*)d_in[2];
    const float* W2    = (const float*)d_in[3];
    const float* b2    = (const float*)d_in[4];
    const float* W_exp = (const float*)d_in[5];
    const float* b_exp = (const float*)d_in[6];
    const float* W_v   = (const float*)d_in[7];
    const float* b_v   = (const float*)d_in[8];
    const float* W_k   = (const float*)d_in[9];
    const float* b_k   = (const float*)d_in[10];
    const float* W_q   = (const float*)d_in[11];
    const float* b_q   = (const float*)d_in[12];
    const float* W_t   = (const float*)d_in[13];
    const float* b_t   = (const float*)d_in[14];
    const float* W_l   = (const float*)d_in[15];
    const float* b_l   = (const float*)d_in[16];
    const int*   tid   = (const int*)d_in[17];
    float* out = (float*)d_out;

    float *pA, *pB, *pC, *pD, *pE, *pF, *pG, *ekq;
    cudaGetSymbolAddress((void**)&pA, g_pA);
    cudaGetSymbolAddress((void**)&pB, g_pB);
    cudaGetSymbolAddress((void**)&pC, g_pC);
    cudaGetSymbolAddress((void**)&pD, g_pD);
    cudaGetSymbolAddress((void**)&pE, g_pE);
    cudaGetSymbolAddress((void**)&pF, g_pF);
    cudaGetSymbolAddress((void**)&pG, g_pG);
    cudaGetSymbolAddress((void**)&ekq, g_ekq);

    // A: partA = splitK(x @ W1)                         16MB, 256 blocks
    gemv_k<128, 32, 2048, 0, 0, 1, false, false, false>
        <<<dim3(4, 64, 1), 128>>>(W1, x, nullptr, nullptr, nullptr, pA);
    // B: h1 = relu(reduce(pA)+b1) fused; partB = splitK(h1 @ W2)     16MB
    gemv_k<128, 32, 2048, 1, 64, 2048, true, false, false>
        <<<dim3(4, 64, 1), 128>>>(W2, pA, b1, nullptr, nullptr, pB);
    // C: h2 fused; partC[n] = splitK(h2 @ W_exp[n])     256MB, 1024 blocks
    gemv_k<128, 128, 2048, 1, 64, 2048, true, false, false>
        <<<dim3(4, 16, 16), 128>>>(W_exp, pB, b2, nullptr, nullptr, pC);
    // D: e[n] fused; partD[n] = splitK(e[n] @ W_k[n])   32MB, 512 blocks
    gemv_k<64, 64, 256, 1, 16, 2048, true, false, true>
        <<<dim3(1, 32, 16), 64>>>(W_k, pC, b_exp, nullptr, nullptr, pD);
    // expkq
    fin_expkq<<<1, 512>>>(pD, b_k, W_q, b_q, tid, ekq);
    // E: e[n] fused; partE[n] = expkq[n] * splitK(e[n] @ W_v[n])  256MB, 1024 blocks
    gemv_k<128, 128, 2048, 1, 16, 2048, true, true, true>
        <<<dim3(4, 16, 16), 128>>>(W_v, pC, b_exp, nullptr, ekq, pE);
    // F: res fused (flat 256-slice reduce + ekq.b_v); partF = splitK(res @ W_t)  16MB
    gemv_k<128, 32, 2048, 2, 256, 2048, false, false, false>
        <<<dim3(4, 64, 1), 128>>>(W_t, pE, nullptr, b_v, ekq, pF);
    // G: t = relu(reduce(pF)+b_t) fused; partG = splitK(t @ W_l)     4MB
    gemv_k<128, 16, 512, 1, 64, 2048, true, false, false>
        <<<dim3(1, 128, 1), 128>>>(W_l, pF, b_t, nullptr, nullptr, pG);
    // out
    fin_out<<<4, 128>>>(pG, b_l, out);
}

// round 3
// speedup vs baseline: 2.4218x; 1.1929x over previous
#include <cuda_runtime.h>
#include <cuda_bf16.h>
#include <cstddef>

// NetAE batch-1 forward: HBM-bound GEMV chain (~596MB fp32 weights/call).
// Split-K GEMV, previous stage's reduction+bias+relu fused into consumer's
// x-staging prologue. Round 3: 256-thread blocks everywhere + row-group (GRP)
// splitting for narrow-N stages -> >=14 warps/SM on every launch.

#define D_H    2048
#define D_A    256
#define N_EXP  16
#define D_OUT  512

__device__ float g_pA[128 * 2048];
__device__ float g_pB[128 * 2048];
__device__ float g_pC[16 * 32 * 2048];
__device__ float g_pD[16 * 128 * 256];
__device__ float g_pE[16 * 32 * 2048];
__device__ float g_pF[128 * 2048];
__device__ float g_pG[256 * 512];
__device__ float g_ekq[16];

// ---------------------------------------------------------------------------
// Split-K GEMV, x-staging prologue fused with previous stage's reduction.
//   MODE 0: x[r] = xsrc[i0+r]
//   MODE 1: x[r] = [relu](biasx[bb*NPREV+i0+r] + sum_{s<SPREV} xsrc[(bb*SPREV+s)*NPREV+i0+r])
//   MODE 2: x[r] = sum_{s<SPREV} xsrc[s*NPREV+i0+r] + sum_n ekq[n]*bv[n*NPREV+i0+r]
// Block: RPS rows x (BLK/GRP)*4 cols, GRP row-groups each writing its own
// partial slice: partOut[((b*S+slice)*GRP+g)*N + j] (float4, no atomics).
// ---------------------------------------------------------------------------
template<int BLK, int RPS, int N, int GRP, int MODE, int SPREV, int NPREV,
         bool RELU_X, bool SCALE_OUT, bool PREV_PER_B>
__global__ __launch_bounds__(BLK)
void gemv_k(const float* __restrict__ W,
            const float* __restrict__ xsrc,
            const float* __restrict__ biasx,
            const float* __restrict__ bv,
            const float* __restrict__ ekq,
            float* __restrict__ partOut)
{
    __shared__ float sx[RPS];
    __shared__ float sxp[BLK];
    const int tid   = threadIdx.x;
    const int slice = blockIdx.y;
    const int b     = blockIdx.z;
    const int S     = gridDim.y;
    const int i0    = slice * RPS;
    const int K     = S * RPS;

    if constexpr (MODE == 0) {
        for (int r = tid; r < RPS; r += BLK) sx[r] = xsrc[i0 + r];
        __syncthreads();
    } else if constexpr (MODE == 1) {
        constexpr int CH = BLK / RPS;
        const int r = tid % RPS;
        const int c = tid / RPS;
        const int bb = PREV_PER_B ? b : 0;
        const float* p = xsrc + ((size_t)bb * SPREV) * NPREV + (i0 + r);
        float v = 0.f;
        #pragma unroll
        for (int s = c; s < SPREV; s += CH) v += p[(size_t)s * NPREV];
        sxp[tid] = v;
        __syncthreads();
        if (tid < RPS) {
            float v2 = biasx[(size_t)(PREV_PER_B ? b : 0) * NPREV + i0 + tid];
            #pragma unroll
            for (int cc = 0; cc < CH; cc++) v2 += sxp[tid + cc * RPS];
            sx[tid] = RELU_X ? fmaxf(v2, 0.f) : v2;
        }
        __syncthreads();
    } else {  // MODE 2: flat reduce over scaled V-partials + ekq-weighted b_v
        constexpr int CH = BLK / RPS;
        const int r = tid % RPS;
        const int c = tid / RPS;
        const float* p = xsrc + (i0 + r);
        float v = 0.f;
        #pragma unroll 16
        for (int s = c; s < SPREV; s += CH) v += p[(size_t)s * NPREV];
        sxp[tid] = v;
        __syncthreads();
        if (tid < RPS) {
            float v2 = 0.f;
            #pragma unroll
            for (int cc = 0; cc < CH; cc++) v2 += sxp[tid + cc * RPS];
            #pragma unroll
            for (int n = 0; n < N_EXP; n++)
                v2 += ekq[n] * bv[(size_t)n * NPREV + i0 + tid];
            sx[tid] = v2;
        }
        __syncthreads();
    }

    constexpr int CT  = BLK / GRP;      // float4 cols handled per group
    constexpr int RPG = RPS / GRP;      // rows per group
    const int g  = tid / CT;
    const int j  = (blockIdx.x * CT + (tid % CT)) * 4;
    const int r0 = g * RPG;

    const float* Wp = W + (size_t)b * K * N + (size_t)(i0 + r0) * N + j;
    float4 acc = make_float4(0.f, 0.f, 0.f, 0.f);
    #pragma unroll 16
    for (int rr = 0; rr < RPG; rr++) {
        const float4 w = *reinterpret_cast<const float4*>(Wp + (size_t)rr * N);
        const float xi = sx[r0 + rr];
        acc.x += xi * w.x;
        acc.y += xi * w.y;
        acc.z += xi * w.z;
        acc.w += xi * w.w;
    }
    if constexpr (SCALE_OUT) {
        const float sc = ekq[b];
        acc.x *= sc; acc.y *= sc; acc.z *= sc; acc.w *= sc;
    }
    *reinterpret_cast<float4*>(
        partOut + ((size_t)((b * S + slice) * GRP + g)) * N + j) = acc;
}

// expkq[n] = (b_k[n] + reduce_{s<128} pD[n]) . (W_q[t][t] + b_q[t])
// one block per expert, 256 threads (thread = one attention dim a)
__global__ __launch_bounds__(256)
void fin_expkq(const float* __restrict__ part,
               const float* __restrict__ b_k,
               const float* __restrict__ W_q,
               const float* __restrict__ b_q,
               const int* __restrict__ task_id,
               float* __restrict__ expkq)
{
    __shared__ float red[256];
    const int n = blockIdx.x;
    const int a = threadIdx.x;
    const int t = *task_id;
    float k = b_k[n * D_A + a];
    const float* p = part + ((size_t)n * 128) * D_A + a;
    #pragma unroll 16
    for (int s = 0; s < 128; s++) k += p[(size_t)s * D_A];
    const float q = W_q[((size_t)t * 10 + t) * D_A + a] + b_q[t * D_A + a];
    red[a] = k * q;
    __syncthreads();
    #pragma unroll
    for (int off = 128; off >= 32; off >>= 1) {
        if (a < off) red[a] += red[a + off];
        __syncthreads();
    }
    if (a < 32) {
        float v = red[a];
        #pragma unroll
        for (int off = 16; off; off >>= 1) v += __shfl_xor_sync(0xFFFFFFFFu, v, off);
        if (a == 0) expkq[n] = v;
    }
}

// out[j] = b_l[j] + reduce_{s<256} pG[s*512 + j];  4 blocks x 256 thr, 2-way depth split
__global__ __launch_bounds__(256)
void fin_out(const float* __restrict__ part,
             const float* __restrict__ b_l,
             float* __restrict__ out)
{
    __shared__ float red[256];
    const int c = threadIdx.x % 128;
    const int h = threadIdx.x / 128;
    const int j = blockIdx.x * 128 + c;
    const float* p = part + (size_t)h * 128 * D_OUT + j;
    float v = 0.f;
    #pragma unroll 16
    for (int s = 0; s < 128; s++) v += p[(size_t)s * D_OUT];
    red[threadIdx.x] = v;
    __syncthreads();
    if (h == 0) out[j] = b_l[j] + red[c] + red[c + 128];
}

extern "C" void kernel_launch(void* const* d_in, const int* in_sizes, int n_in,
                              void* d_out, int out_size)
{
    const float* x     = (const float*)d_in[0];
    const float* W1    = (const float*)d_in[1];
    const float* b1    = (const float*)d_in[2];
    const float* W2    = (const float*)d_in[3];
    const float* b2    = (const float*)d_in[4];
    const float* W_exp = (const float*)d_in[5];
    const float* b_exp = (const float*)d_in[6];
    const float* W_v   = (const float*)d_in[7];
    const float* b_v   = (const float*)d_in[8];
    const float* W_k   = (const float*)d_in[9];
    const float* b_k   = (const float*)d_in[10];
    const float* W_q   = (const float*)d_in[11];
    const float* b_q   = (const float*)d_in[12];
    const float* W_t   = (const float*)d_in[13];
    const float* b_t   = (const float*)d_in[14];
    const float* W_l   = (const float*)d_in[15];
    const float* b_l   = (const float*)d_in[16];
    const int*   tid   = (const int*)d_in[17];
    float* out = (float*)d_out;

    float *pA, *pB, *pC, *pD, *pE, *pF, *pG, *ekq;
    cudaGetSymbolAddress((void**)&pA, g_pA);
    cudaGetSymbolAddress((void**)&pB, g_pB);
    cudaGetSymbolAddress((void**)&pC, g_pC);
    cudaGetSymbolAddress((void**)&pD, g_pD);
    cudaGetSymbolAddress((void**)&pE, g_pE);
    cudaGetSymbolAddress((void**)&pF, g_pF);
    cudaGetSymbolAddress((void**)&pG, g_pG);
    cudaGetSymbolAddress((void**)&ekq, g_ekq);

    // A: pA = splitK(x @ W1)                  16MB, 256 blk x 8 warps
    gemv_k<256, 16, 2048, 1, 0, 0, 1, false, false, false>
        <<<dim3(2, 128, 1), 256>>>(W1, x, nullptr, nullptr, nullptr, pA);
    // B: h1 fused; pB = splitK(h1 @ W2)       16MB
    gemv_k<256, 16, 2048, 1, 1, 128, 2048, true, false, false>
        <<<dim3(2, 128, 1), 256>>>(W2, pA, b1, nullptr, nullptr, pB);
    // C: h2 fused; pC[n] = splitK(h2 @ W_exp[n])   256MB, 1024 blk x 8 warps
    gemv_k<256, 64, 2048, 1, 1, 128, 2048, true, false, false>
        <<<dim3(2, 32, 16), 256>>>(W_exp, pB, b2, nullptr, nullptr, pC);
    // D: e[n] fused; pD[n] = splitK(e[n] @ W_k[n])  32MB, 512 blk x 8 warps, GRP=4
    gemv_k<256, 64, 256, 4, 1, 32, 2048, true, false, true>
        <<<dim3(1, 32, 16), 256>>>(W_k, pC, b_exp, nullptr, nullptr, pD);
    // expkq: one block per expert
    fin_expkq<<<16, 256>>>(pD, b_k, W_q, b_q, tid, ekq);
    // E: e[n] fused; pE[n] = ekq[n] * splitK(e[n] @ W_v[n])   256MB
    gemv_k<256, 64, 2048, 1, 1, 32, 2048, true, true, true>
        <<<dim3(2, 32, 16), 256>>>(W_v, pC, b_exp, nullptr, ekq, pE);
    // F: res fused (512-slice flat reduce + ekq.b_v); pF = splitK(res @ W_t)  16MB
    gemv_k<256, 16, 2048, 1, 2, 512, 2048, false, false, false>
        <<<dim3(2, 128, 1), 256>>>(W_t, pE, nullptr, b_v, ekq, pF);
    // G: t fused; pG = splitK(t @ W_l)        4MB, 128 blk x 8 warps, GRP=2
    gemv_k<256, 16, 512, 2, 1, 128, 2048, true, false, false>
        <<<dim3(1, 128, 1), 256>>>(W_l, pF, b_t, nullptr, nullptr, pG);
    // out
    fin_out<<<4, 256>>>(pG, b_l, out);
}